// round 1
// baseline (speedup 1.0000x reference)
#include <cuda_runtime.h>

#define NTOK 49
#define CDIM 128
#define NHEAD 4
#define HDIM 32
#define NWIN 64
#define THREADS 512

// ---- shared memory layout (in floats) ----
#define XS_OFF   0
#define XS_SZ    (NTOK * CDIM)            // 6272 (x tile, later reused as attn-out buffer)
#define QKV_STR  36                       // padded head-dim stride (32 -> 36, 16B aligned)
#define HEAD_SZ  (NTOK * QKV_STR)         // 1764
#define QS_OFF   (XS_OFF + XS_SZ)         // 6272
#define KS_OFF   (QS_OFF + NHEAD * HEAD_SZ)
#define VS_OFF   (KS_OFF + NHEAD * HEAD_SZ)
#define WT_OFF   (VS_OFF + NHEAD * HEAD_SZ)   // 27440: weight tile region / attn region
#define WT_STR   132                      // 128 + 4 pad, 16B aligned rows
#define WT_SZ    (128 * WT_STR)           // 16896  (attn needs 4*49*49 = 9604, fits inside)
#define SMEM_FLOATS (WT_OFF + WT_SZ)      // 44336 floats = 177344 bytes

__global__ __launch_bounds__(THREADS, 1)
void window_attn_kernel(const float* __restrict__ x,
                        const float* __restrict__ mask,
                        const float* __restrict__ qkv_w,
                        const float* __restrict__ qkv_b,
                        const float* __restrict__ proj_w,
                        const float* __restrict__ proj_b,
                        const float* __restrict__ bias_table,
                        float* __restrict__ out)
{
    extern __shared__ float s[];
    float* xs   = s + XS_OFF;
    float* qs   = s + QS_OFF;
    float* ks_  = s + KS_OFF;
    float* vs   = s + VS_OFF;
    float* wt   = s + WT_OFF;   // weight tile
    float* attn = s + WT_OFF;   // reused for attention scores

    const int tid = threadIdx.x;
    const int b   = blockIdx.x;
    const float scale = 0.17677669529663687f;  // 32^-0.5

    // ---- Phase 1: load x tile [49,128] ----
    {
        const float* xb = x + (size_t)b * (NTOK * CDIM);
        for (int i = tid; i < NTOK * CDIM; i += THREADS) xs[i] = xb[i];
    }
    __syncthreads();

    const int jl = tid & 127;   // column within weight tile
    const int n0 = tid >> 7;    // 0..3

    // ---- Phase 2: QKV = x @ qkv_w^T + qkv_b  (3 tiles of 128 output cols) ----
    for (int j0 = 0; j0 < 3 * CDIM; j0 += 128) {
        // cooperative stage of 128x128 weight tile, padded rows
        for (int i = tid; i < 128 * 128; i += THREADS) {
            int r = i >> 7, c = i & 127;
            wt[r * WT_STR + c] = qkv_w[(size_t)(j0 + r) * CDIM + c];
        }
        __syncthreads();

        const int j    = j0 + jl;
        const int comp = j >> 7;         // 0=q,1=k,2=v (one comp per tile)
        const int cc   = j & 127;
        const int h    = cc >> 5;
        const int d    = cc & 31;
        const float bj = qkv_b[j];
        float* dst = (comp == 0) ? qs : (comp == 1) ? ks_ : vs;
        const float mul = (comp == 0) ? scale : 1.0f;

        float acc[13];
#pragma unroll
        for (int sidx = 0; sidx < 13; sidx++) acc[sidx] = 0.0f;

        const float4* wr = (const float4*)(wt + jl * WT_STR);
#pragma unroll 4
        for (int k4 = 0; k4 < CDIM / 4; k4++) {
            float4 wv = wr[k4];
#pragma unroll
            for (int sidx = 0; sidx < 13; sidx++) {
                int n = n0 + 4 * sidx;          // may read up to row 51 (garbage, discarded)
                float4 xv = ((const float4*)(xs + n * CDIM))[k4];
                acc[sidx] += xv.x * wv.x + xv.y * wv.y + xv.z * wv.z + xv.w * wv.w;
            }
        }
#pragma unroll
        for (int sidx = 0; sidx < 13; sidx++) {
            int n = n0 + 4 * sidx;
            if (n < NTOK) dst[h * HEAD_SZ + n * QKV_STR + d] = (acc[sidx] + bj) * mul;
        }
        __syncthreads();
    }

    // ---- Phase 3: attn[h][i][j] = q.k + rel_bias + mask ----
    {
        const float* mrow = mask + (size_t)(b & (NWIN - 1)) * (NTOK * NTOK);
        for (int o = tid; o < NHEAD * NTOK * NTOK; o += THREADS) {
            int h = o / (NTOK * NTOK);
            int r = o - h * (NTOK * NTOK);
            int i = r / NTOK;
            int j = r - i * NTOK;
            const float4* q4 = (const float4*)(qs + h * HEAD_SZ + i * QKV_STR);
            const float4* k4 = (const float4*)(ks_ + h * HEAD_SZ + j * QKV_STR);
            float a0 = 0.f, a1 = 0.f, a2 = 0.f, a3 = 0.f;
#pragma unroll
            for (int d4 = 0; d4 < HDIM / 4; d4++) {
                float4 qv = q4[d4], kv = k4[d4];
                a0 += qv.x * kv.x; a1 += qv.y * kv.y;
                a2 += qv.z * kv.z; a3 += qv.w * kv.w;
            }
            int ih = i / 7, iw = i - 7 * ih;
            int jh = j / 7, jw = j - 7 * jh;
            int ridx = (ih - jh + 6) * 13 + (iw - jw + 6);
            attn[o] = (a0 + a1) + (a2 + a3) + bias_table[ridx * NHEAD + h] + mrow[i * NTOK + j];
        }
    }
    __syncthreads();

    // ---- Phase 4: softmax over last dim (one thread per (h,i) row) ----
    if (tid < NHEAD * NTOK) {
        float* row = attn + tid * NTOK;
        float m = row[0];
#pragma unroll
        for (int j = 1; j < NTOK; j++) m = fmaxf(m, row[j]);
        float ssum = 0.f;
#pragma unroll
        for (int j = 0; j < NTOK; j++) { float e = __expf(row[j] - m); row[j] = e; ssum += e; }
        float inv = 1.0f / ssum;
#pragma unroll
        for (int j = 0; j < NTOK; j++) row[j] *= inv;
    }
    __syncthreads();

    // ---- Phase 5: out[n][h*32+d] = attn @ v  (vectorized over d, into xs) ----
    for (int o = tid; o < (NTOK * CDIM) / 4; o += THREADS) {
        int idx = o * 4;
        int i = idx >> 7;
        int c = idx & 127;
        int h = c >> 5;
        int d = c & 31;
        const float* arow = attn + h * (NTOK * NTOK) + i * NTOK;
        const float* vbase = vs + h * HEAD_SZ + d;
        float4 acc = make_float4(0.f, 0.f, 0.f, 0.f);
#pragma unroll 7
        for (int j = 0; j < NTOK; j++) {
            float a = arow[j];
            float4 vv = *(const float4*)(vbase + j * QKV_STR);
            acc.x += a * vv.x; acc.y += a * vv.y; acc.z += a * vv.z; acc.w += a * vv.w;
        }
        *(float4*)(xs + idx) = acc;
    }
    __syncthreads();

    // ---- Phase 6: final = outbuf @ proj_w^T + proj_b ----
    {
        for (int i = tid; i < 128 * 128; i += THREADS) {
            int r = i >> 7, c = i & 127;
            wt[r * WT_STR + c] = proj_w[(size_t)r * CDIM + c];
        }
        __syncthreads();

        const int c  = jl;
        const float pb = proj_b[c];
        float* ob = out + (size_t)b * (NTOK * CDIM);

        float acc[13];
#pragma unroll
        for (int sidx = 0; sidx < 13; sidx++) acc[sidx] = 0.0f;

        const float4* wr = (const float4*)(wt + c * WT_STR);
#pragma unroll 4
        for (int k4 = 0; k4 < CDIM / 4; k4++) {
            float4 wv = wr[k4];
#pragma unroll
            for (int sidx = 0; sidx < 13; sidx++) {
                int n = n0 + 4 * sidx;
                float4 xv = ((const float4*)(xs + n * CDIM))[k4];
                acc[sidx] += xv.x * wv.x + xv.y * wv.y + xv.z * wv.z + xv.w * wv.w;
            }
        }
#pragma unroll
        for (int sidx = 0; sidx < 13; sidx++) {
            int n = n0 + 4 * sidx;
            if (n < NTOK) ob[n * CDIM + c] = acc[sidx] + pb;
        }
    }
}

extern "C" void kernel_launch(void* const* d_in, const int* in_sizes, int n_in,
                              void* d_out, int out_size)
{
    const float* x          = (const float*)d_in[0];
    const float* mask       = (const float*)d_in[1];
    const float* qkv_w      = (const float*)d_in[2];
    const float* qkv_b      = (const float*)d_in[3];
    const float* proj_w     = (const float*)d_in[4];
    const float* proj_b     = (const float*)d_in[5];
    const float* bias_table = (const float*)d_in[6];
    float* out = (float*)d_out;

    const int B = in_sizes[0] / (NTOK * CDIM);   // 8192
    const int smem_bytes = SMEM_FLOATS * (int)sizeof(float);

    cudaFuncSetAttribute(window_attn_kernel,
                         cudaFuncAttributeMaxDynamicSharedMemorySize, smem_bytes);

    window_attn_kernel<<<B, THREADS, smem_bytes>>>(
        x, mask, qkv_w, qkv_b, proj_w, proj_b, bias_table, out);
}

// round 2
// speedup vs baseline: 2.9557x; 2.9557x over previous
#include <cuda_runtime.h>
#include <cstdint>

#define NTOK 49
#define CDIM 128
#define NHEAD 4
#define NWIN 64
#define THREADS 512

// ---- shared memory layout (float offsets) ----
#define XS_STR 132
#define XS_OFF 0
#define XS_SZ  (64 * XS_STR)          // 8448  : x tile / attn-out tile (A operands)
#define R2_OFF (XS_OFF + XS_SZ)       // 8448  : weight tile [128][132] OR attn [4][64][60]
#define R2_SZ  (128 * 132)            // 16896
#define WS_STR 132
#define AT_STR 60
#define AT_HSZ (64 * AT_STR)          // 3840 per head
#define QKV_OFF (R2_OFF + R2_SZ)      // 25344 : q/k/v [3][4 heads][64][36]
#define QK_STR 36
#define QK_HSZ (64 * QK_STR)          // 2304
#define QK_CSZ (NHEAD * QK_HSZ)       // 9216
#define SMEM_FLOATS (QKV_OFF + 3 * QK_CSZ)   // 52992 floats = 211968 bytes

__device__ __forceinline__ float f2tf(float f) {
    uint32_t u;
    asm("cvt.rna.tf32.f32 %0, %1;" : "=r"(u) : "f"(f));
    return __uint_as_float(u);
}
__device__ __forceinline__ uint32_t fau(float f) { return __float_as_uint(f); }

__device__ __forceinline__ void mma8(float c[4], const uint32_t a[4], const uint32_t b[2]) {
    asm volatile(
        "mma.sync.aligned.m16n8k8.row.col.f32.tf32.tf32.f32 "
        "{%0,%1,%2,%3},{%4,%5,%6,%7},{%8,%9},{%0,%1,%2,%3};\n"
        : "+f"(c[0]), "+f"(c[1]), "+f"(c[2]), "+f"(c[3])
        : "r"(a[0]), "r"(a[1]), "r"(a[2]), "r"(a[3]), "r"(b[0]), "r"(b[1]));
}

__global__ __launch_bounds__(THREADS, 1)
void window_attn_tc(const float* __restrict__ x,
                    const float* __restrict__ mask,
                    const float* __restrict__ qkv_w,
                    const float* __restrict__ qkv_b,
                    const float* __restrict__ proj_w,
                    const float* __restrict__ proj_b,
                    const float* __restrict__ bias_table,
                    float* __restrict__ out)
{
    extern __shared__ float s[];
    float* xs = s + XS_OFF;           // [64][132] tf32: x tile, later attn-out tile
    float* r2 = s + R2_OFF;           // weight tile or attn scores

    const int tid  = threadIdx.x;
    const int wid  = tid >> 5;
    const int lane = tid & 31;
    const int g    = lane >> 2;       // group id 0..7 (row within fragment)
    const int t    = lane & 3;        // thread-in-group 0..3
    const int b    = blockIdx.x;
    const float scale = 0.17677669529663687f;   // 32^-0.5

    // ---- Phase 1: load x tile (tf32), zero-pad rows 49..63 ----
    {
        const float4* xb = (const float4*)(x + (size_t)b * (NTOK * CDIM));
        for (int i = tid; i < 64 * 32; i += THREADS) {
            int r = i >> 5, c4 = i & 31;
            float4 v = (r < NTOK) ? xb[r * 32 + c4] : make_float4(0.f, 0.f, 0.f, 0.f);
            float* d = xs + r * XS_STR + c4 * 4;
            d[0] = f2tf(v.x); d[1] = f2tf(v.y); d[2] = f2tf(v.z); d[3] = f2tf(v.w);
        }
    }
    __syncthreads();

    // ---- Phase 2: QKV = x @ qkv_w^T + b ; q scaled. 3 chunks of 128 cols ----
    for (int ch = 0; ch < 3; ch++) {
        {
            const float4* wg = (const float4*)(qkv_w + (size_t)ch * 128 * CDIM);
            for (int i = tid; i < 128 * 32; i += THREADS) {
                int r = i >> 5, c4 = i & 31;
                float4 v = wg[r * 32 + c4];
                float* d = r2 + r * WS_STR + c4 * 4;
                d[0] = f2tf(v.x); d[1] = f2tf(v.y); d[2] = f2tf(v.z); d[3] = f2tf(v.w);
            }
        }
        __syncthreads();

        const int mi = wid & 3;       // M-tile (16 rows)
        const int nq = wid >> 2;      // 32-col group
        const int r0 = mi * 16 + g;

        float acc[4][4];
#pragma unroll
        for (int i = 0; i < 4; i++)
#pragma unroll
            for (int j = 0; j < 4; j++) acc[i][j] = 0.f;

#pragma unroll
        for (int ks = 0; ks < 16; ks++) {
            const int k0 = ks * 8;
            const float* ar = xs + r0 * XS_STR + k0 + t;
            uint32_t a[4] = { fau(ar[0]), fau(ar[8 * XS_STR]),
                              fau(ar[4]), fau(ar[8 * XS_STR + 4]) };
#pragma unroll
            for (int nt = 0; nt < 4; nt++) {
                const float* br = r2 + (nq * 32 + nt * 8 + g) * WS_STR + k0 + t;
                uint32_t bb[2] = { fau(br[0]), fau(br[4]) };
                mma8(acc[nt], a, bb);
            }
        }

        // epilogue -> q/k/v smem (tf32)
        {
            const float mul = (ch == 0) ? scale : 1.f;
            float* dst = s + QKV_OFF + ch * QK_CSZ;
#pragma unroll
            for (int nt = 0; nt < 4; nt++) {
                const int c0 = nq * 32 + nt * 8 + 2 * t;
#pragma unroll
                for (int e = 0; e < 4; e++) {
                    const int rr = r0 + ((e >= 2) ? 8 : 0);
                    const int cc = c0 + (e & 1);
                    const int h = cc >> 5, dd = cc & 31;
                    float v = (acc[nt][e] + qkv_b[ch * 128 + cc]) * mul;
                    dst[h * QK_HSZ + rr * QK_STR + dd] = f2tf(v);
                }
            }
        }
        __syncthreads();
    }

    // ---- Phase 3: scores = q k^T + rel_bias + mask -> attn [4][64][60] ----
    {
        const int h  = wid >> 2;
        const int mi = wid & 3;
        const int r0 = mi * 16 + g;
        const float* qh = s + QKV_OFF + 0 * QK_CSZ + h * QK_HSZ;
        const float* kh = s + QKV_OFF + 1 * QK_CSZ + h * QK_HSZ;

        float acc[7][4];
#pragma unroll
        for (int i = 0; i < 7; i++)
#pragma unroll
            for (int j = 0; j < 4; j++) acc[i][j] = 0.f;

#pragma unroll
        for (int ks = 0; ks < 4; ks++) {
            const int k0 = ks * 8;
            const float* ar = qh + r0 * QK_STR + k0 + t;
            uint32_t a[4] = { fau(ar[0]), fau(ar[8 * QK_STR]),
                              fau(ar[4]), fau(ar[8 * QK_STR + 4]) };
#pragma unroll
            for (int nt = 0; nt < 7; nt++) {
                const float* br = kh + (nt * 8 + g) * QK_STR + k0 + t;
                uint32_t bb[2] = { fau(br[0]), fau(br[4]) };
                mma8(acc[nt], a, bb);
            }
        }

        float* at = r2 + h * AT_HSZ;
        const float* mrow = mask + (size_t)(b & (NWIN - 1)) * (NTOK * NTOK);
        const int rA = r0, rB = r0 + 8;
        const int ihA = rA / 7, iwA = rA - 7 * ihA;
        const int ihB = rB / 7, iwB = rB - 7 * ihB;
#pragma unroll
        for (int nt = 0; nt < 7; nt++) {
            const int c0 = nt * 8 + 2 * t;
#pragma unroll
            for (int e = 0; e < 4; e++) {
                const int rr = (e >= 2) ? rB : rA;
                const int jj = c0 + (e & 1);
                float v = 0.f;
                if (rr < NTOK && jj < NTOK) {
                    const int ih = (e >= 2) ? ihB : ihA;
                    const int iw = (e >= 2) ? iwB : iwA;
                    const int jh = jj / 7, jw = jj - 7 * jh;
                    const int ridx = (ih - jh + 6) * 13 + (iw - jw + 6);
                    v = acc[nt][e] + bias_table[ridx * NHEAD + h] + mrow[rr * NTOK + jj];
                }
                at[rr * AT_STR + jj] = v;
            }
        }
    }
    __syncthreads();

    // ---- Phase 4: softmax per (h, i<49) row; write tf32 probs ----
    if (tid < NHEAD * NTOK) {
        const int h = tid / NTOK;
        const int i = tid - h * NTOK;
        float* row = r2 + h * AT_HSZ + i * AT_STR;
        float m = row[0];
#pragma unroll
        for (int j = 1; j < NTOK; j++) m = fmaxf(m, row[j]);
        float ssum = 0.f;
        float e49[49];
#pragma unroll
        for (int j = 0; j < NTOK; j++) { e49[j] = __expf(row[j] - m); ssum += e49[j]; }
        const float inv = 1.0f / ssum;
#pragma unroll
        for (int j = 0; j < NTOK; j++) row[j] = f2tf(e49[j] * inv);
    }
    __syncthreads();

    // ---- Phase 5: o = attn @ v -> xs [64][132] (cols h*32+d), tf32 ----
    {
        const int h  = wid >> 2;
        const int mi = wid & 3;
        const int r0 = mi * 16 + g;
        const float* at = r2 + h * AT_HSZ;
        const float* vh = s + QKV_OFF + 2 * QK_CSZ + h * QK_HSZ;

        float acc[4][4];
#pragma unroll
        for (int i = 0; i < 4; i++)
#pragma unroll
            for (int j = 0; j < 4; j++) acc[i][j] = 0.f;

#pragma unroll
        for (int ks = 0; ks < 7; ks++) {
            const int k0 = ks * 8;
            const float* ar = at + r0 * AT_STR + k0 + t;
            uint32_t a[4] = { fau(ar[0]), fau(ar[8 * AT_STR]),
                              fau(ar[4]), fau(ar[8 * AT_STR + 4]) };
#pragma unroll
            for (int nt = 0; nt < 4; nt++) {
                const float* br = vh + (k0 + t) * QK_STR + nt * 8 + g;
                uint32_t bb[2] = { fau(br[0]), fau(br[4 * QK_STR]) };
                mma8(acc[nt], a, bb);
            }
        }
        __syncthreads();   // attn reads done before r2 is overwritten with proj_w

#pragma unroll
        for (int nt = 0; nt < 4; nt++) {
            const int c0 = nt * 8 + 2 * t;
#pragma unroll
            for (int e = 0; e < 4; e++) {
                const int rr = r0 + ((e >= 2) ? 8 : 0);
                const int dd = c0 + (e & 1);
                xs[rr * XS_STR + h * 32 + dd] = f2tf(acc[nt][e]);
            }
        }
    }
    __syncthreads();

    // ---- Phase 6: final = o @ proj_w^T + proj_b ----
    {
        const float4* wg = (const float4*)proj_w;
        for (int i = tid; i < 128 * 32; i += THREADS) {
            int r = i >> 5, c4 = i & 31;
            float4 v = wg[r * 32 + c4];
            float* d = r2 + r * WS_STR + c4 * 4;
            d[0] = f2tf(v.x); d[1] = f2tf(v.y); d[2] = f2tf(v.z); d[3] = f2tf(v.w);
        }
        __syncthreads();

        const int mi = wid & 3;
        const int nq = wid >> 2;
        const int r0 = mi * 16 + g;

        float acc[4][4];
#pragma unroll
        for (int i = 0; i < 4; i++)
#pragma unroll
            for (int j = 0; j < 4; j++) acc[i][j] = 0.f;

#pragma unroll
        for (int ks = 0; ks < 16; ks++) {
            const int k0 = ks * 8;
            const float* ar = xs + r0 * XS_STR + k0 + t;
            uint32_t a[4] = { fau(ar[0]), fau(ar[8 * XS_STR]),
                              fau(ar[4]), fau(ar[8 * XS_STR + 4]) };
#pragma unroll
            for (int nt = 0; nt < 4; nt++) {
                const float* br = r2 + (nq * 32 + nt * 8 + g) * WS_STR + k0 + t;
                uint32_t bb[2] = { fau(br[0]), fau(br[4]) };
                mma8(acc[nt], a, bb);
            }
        }

        // stage into smem (QKV region, free now) for coalesced global store
        float* os = s + QKV_OFF;      // [64][132]
#pragma unroll
        for (int nt = 0; nt < 4; nt++) {
            const int c0 = nq * 32 + nt * 8 + 2 * t;
#pragma unroll
            for (int e = 0; e < 4; e++) {
                const int rr = r0 + ((e >= 2) ? 8 : 0);
                const int cc = c0 + (e & 1);
                os[rr * XS_STR + cc] = acc[nt][e] + proj_b[cc];
            }
        }
        __syncthreads();

        float4* ob = (float4*)(out + (size_t)b * (NTOK * CDIM));
        for (int i = tid; i < NTOK * 32; i += THREADS) {
            int r = i >> 5, c4 = i & 31;
            const float* p = os + r * XS_STR + c4 * 4;
            ob[r * 32 + c4] = make_float4(p[0], p[1], p[2], p[3]);
        }
    }
}

extern "C" void kernel_launch(void* const* d_in, const int* in_sizes, int n_in,
                              void* d_out, int out_size)
{
    const float* x          = (const float*)d_in[0];
    const float* mask       = (const float*)d_in[1];
    const float* qkv_w      = (const float*)d_in[2];
    const float* qkv_b      = (const float*)d_in[3];
    const float* proj_w     = (const float*)d_in[4];
    const float* proj_b     = (const float*)d_in[5];
    const float* bias_table = (const float*)d_in[6];
    float* out = (float*)d_out;

    const int B = in_sizes[0] / (NTOK * CDIM);   // 8192
    const int smem_bytes = SMEM_FLOATS * (int)sizeof(float);

    cudaFuncSetAttribute(window_attn_tc,
                         cudaFuncAttributeMaxDynamicSharedMemorySize, smem_bytes);

    window_attn_tc<<<B, THREADS, smem_bytes>>>(
        x, mask, qkv_w, qkv_b, proj_w, proj_b, bias_table, out);
}

// round 3
// speedup vs baseline: 2.9619x; 1.0021x over previous
#include <cuda_runtime.h>
#include <cstdint>

#define NTOK 49
#define CDIM 128
#define NHEAD 4
#define NWIN 64
#define THREADS 512

// ---- shared memory layout (float offsets) ----
#define XS_STR 132
#define XS_OFF 0
#define XS_SZ  (64 * XS_STR)          // 8448  : x tile / attn-out tile (A operands)
#define R2_OFF (XS_OFF + XS_SZ)       // 8448  : weight tile [128][132] OR attn [4][64][60]
#define R2_SZ  (128 * 132)            // 16896
#define WS_STR 132
#define AT_STR 60
#define AT_HSZ (64 * AT_STR)          // 3840 per head
#define QKV_OFF (R2_OFF + R2_SZ)      // 25344 : q/k/v [3][4 heads][64][36]
#define QK_STR 36
#define QK_HSZ (64 * QK_STR)          // 2304
#define QK_CSZ (NHEAD * QK_HSZ)       // 9216
#define SMEM_FLOATS (QKV_OFF + 3 * QK_CSZ)   // 52992 floats = 211968 bytes

__device__ __forceinline__ float f2tf(float f) {
    uint32_t u;
    asm("cvt.rna.tf32.f32 %0, %1;" : "=r"(u) : "f"(f));
    return __uint_as_float(u);
}
__device__ __forceinline__ uint32_t fau(float f) { return __float_as_uint(f); }

__device__ __forceinline__ void mma8(float c[4], const uint32_t a[4], const uint32_t b[2]) {
    asm volatile(
        "mma.sync.aligned.m16n8k8.row.col.f32.tf32.tf32.f32 "
        "{%0,%1,%2,%3},{%4,%5,%6,%7},{%8,%9},{%0,%1,%2,%3};\n"
        : "+f"(c[0]), "+f"(c[1]), "+f"(c[2]), "+f"(c[3])
        : "r"(a[0]), "r"(a[1]), "r"(a[2]), "r"(a[3]), "r"(b[0]), "r"(b[1]));
}

__global__ __launch_bounds__(THREADS, 1)
void window_attn_tc(const float* __restrict__ x,
                    const float* __restrict__ mask,
                    const float* __restrict__ qkv_w,
                    const float* __restrict__ qkv_b,
                    const float* __restrict__ proj_w,
                    const float* __restrict__ proj_b,
                    const float* __restrict__ bias_table,
                    float* __restrict__ out)
{
    extern __shared__ float s[];
    float* xs = s + XS_OFF;           // [64][132] tf32: x tile, later attn-out tile
    float* r2 = s + R2_OFF;           // weight tile or attn scores

    const int tid  = threadIdx.x;
    const int wid  = tid >> 5;
    const int lane = tid & 31;
    const int g    = lane >> 2;       // group id 0..7 (row within fragment)
    const int t    = lane & 3;        // thread-in-group 0..3
    const int b    = blockIdx.x;
    const float scale = 0.17677669529663687f;   // 32^-0.5

    // ---- Phase 1: load x tile (tf32), zero-pad rows 49..63 ----
    {
        const float4* xb = (const float4*)(x + (size_t)b * (NTOK * CDIM));
        for (int i = tid; i < 64 * 32; i += THREADS) {
            int r = i >> 5, c4 = i & 31;
            float4 v = (r < NTOK) ? xb[r * 32 + c4] : make_float4(0.f, 0.f, 0.f, 0.f);
            float* d = xs + r * XS_STR + c4 * 4;
            d[0] = f2tf(v.x); d[1] = f2tf(v.y); d[2] = f2tf(v.z); d[3] = f2tf(v.w);
        }
    }
    __syncthreads();

    // ---- Phase 2: QKV = x @ qkv_w^T + b ; q scaled. 3 chunks of 128 cols ----
    for (int ch = 0; ch < 3; ch++) {
        {
            const float4* wg = (const float4*)(qkv_w + (size_t)ch * 128 * CDIM);
            for (int i = tid; i < 128 * 32; i += THREADS) {
                int r = i >> 5, c4 = i & 31;
                float4 v = wg[r * 32 + c4];
                float* d = r2 + r * WS_STR + c4 * 4;
                d[0] = f2tf(v.x); d[1] = f2tf(v.y); d[2] = f2tf(v.z); d[3] = f2tf(v.w);
            }
        }
        __syncthreads();

        const int mi = wid & 3;       // M-tile (16 rows)
        const int nq = wid >> 2;      // 32-col group
        const int r0 = mi * 16 + g;

        float acc[4][4];
#pragma unroll
        for (int i = 0; i < 4; i++)
#pragma unroll
            for (int j = 0; j < 4; j++) acc[i][j] = 0.f;

#pragma unroll
        for (int ks = 0; ks < 16; ks++) {
            const int k0 = ks * 8;
            const float* ar = xs + r0 * XS_STR + k0 + t;
            uint32_t a[4] = { fau(ar[0]), fau(ar[8 * XS_STR]),
                              fau(ar[4]), fau(ar[8 * XS_STR + 4]) };
#pragma unroll
            for (int nt = 0; nt < 4; nt++) {
                const float* br = r2 + (nq * 32 + nt * 8 + g) * WS_STR + k0 + t;
                uint32_t bb[2] = { fau(br[0]), fau(br[4]) };
                mma8(acc[nt], a, bb);
            }
        }

        // epilogue -> q/k/v smem (tf32)
        {
            const float mul = (ch == 0) ? scale : 1.f;
            float* dst = s + QKV_OFF + ch * QK_CSZ;
#pragma unroll
            for (int nt = 0; nt < 4; nt++) {
                const int c0 = nq * 32 + nt * 8 + 2 * t;
#pragma unroll
                for (int e = 0; e < 4; e++) {
                    const int rr = r0 + ((e >= 2) ? 8 : 0);
                    const int cc = c0 + (e & 1);
                    const int h = cc >> 5, dd = cc & 31;
                    float v = (acc[nt][e] + qkv_b[ch * 128 + cc]) * mul;
                    dst[h * QK_HSZ + rr * QK_STR + dd] = f2tf(v);
                }
            }
        }
        __syncthreads();
    }

    // ---- Phase 3: scores = q k^T + rel_bias + mask -> attn [4][64][60] ----
    {
        const int h  = wid >> 2;
        const int mi = wid & 3;
        const int r0 = mi * 16 + g;
        const float* qh = s + QKV_OFF + 0 * QK_CSZ + h * QK_HSZ;
        const float* kh = s + QKV_OFF + 1 * QK_CSZ + h * QK_HSZ;

        float acc[7][4];
#pragma unroll
        for (int i = 0; i < 7; i++)
#pragma unroll
            for (int j = 0; j < 4; j++) acc[i][j] = 0.f;

#pragma unroll
        for (int ks = 0; ks < 4; ks++) {
            const int k0 = ks * 8;
            const float* ar = qh + r0 * QK_STR + k0 + t;
            uint32_t a[4] = { fau(ar[0]), fau(ar[8 * QK_STR]),
                              fau(ar[4]), fau(ar[8 * QK_STR + 4]) };
#pragma unroll
            for (int nt = 0; nt < 7; nt++) {
                const float* br = kh + (nt * 8 + g) * QK_STR + k0 + t;
                uint32_t bb[2] = { fau(br[0]), fau(br[4]) };
                mma8(acc[nt], a, bb);
            }
        }

        float* at = r2 + h * AT_HSZ;
        const float* mrow = mask + (size_t)(b & (NWIN - 1)) * (NTOK * NTOK);
        const int rA = r0, rB = r0 + 8;
        const int ihA = rA / 7, iwA = rA - 7 * ihA;
        const int ihB = rB / 7, iwB = rB - 7 * ihB;
#pragma unroll
        for (int nt = 0; nt < 7; nt++) {
            const int c0 = nt * 8 + 2 * t;
#pragma unroll
            for (int e = 0; e < 4; e++) {
                const int rr = (e >= 2) ? rB : rA;
                const int jj = c0 + (e & 1);
                float v = 0.f;
                if (rr < NTOK && jj < NTOK) {
                    const int ih = (e >= 2) ? ihB : ihA;
                    const int iw = (e >= 2) ? iwB : iwA;
                    const int jh = jj / 7, jw = jj - 7 * jh;
                    const int ridx = (ih - jh + 6) * 13 + (iw - jw + 6);
                    v = acc[nt][e] + bias_table[ridx * NHEAD + h] + mrow[rr * NTOK + jj];
                }
                at[rr * AT_STR + jj] = v;
            }
        }
    }
    __syncthreads();

    // ---- Phase 4: softmax per (h, i<49) row; write tf32 probs ----
    if (tid < NHEAD * NTOK) {
        const int h = tid / NTOK;
        const int i = tid - h * NTOK;
        float* row = r2 + h * AT_HSZ + i * AT_STR;
        float m = row[0];
#pragma unroll
        for (int j = 1; j < NTOK; j++) m = fmaxf(m, row[j]);
        float ssum = 0.f;
        float e49[49];
#pragma unroll
        for (int j = 0; j < NTOK; j++) { e49[j] = __expf(row[j] - m); ssum += e49[j]; }
        const float inv = 1.0f / ssum;
#pragma unroll
        for (int j = 0; j < NTOK; j++) row[j] = f2tf(e49[j] * inv);
    }
    __syncthreads();

    // ---- Phase 5: o = attn @ v -> xs [64][132] (cols h*32+d), tf32 ----
    {
        const int h  = wid >> 2;
        const int mi = wid & 3;
        const int r0 = mi * 16 + g;
        const float* at = r2 + h * AT_HSZ;
        const float* vh = s + QKV_OFF + 2 * QK_CSZ + h * QK_HSZ;

        float acc[4][4];
#pragma unroll
        for (int i = 0; i < 4; i++)
#pragma unroll
            for (int j = 0; j < 4; j++) acc[i][j] = 0.f;

#pragma unroll
        for (int ks = 0; ks < 7; ks++) {
            const int k0 = ks * 8;
            const float* ar = at + r0 * AT_STR + k0 + t;
            uint32_t a[4] = { fau(ar[0]), fau(ar[8 * AT_STR]),
                              fau(ar[4]), fau(ar[8 * AT_STR + 4]) };
#pragma unroll
            for (int nt = 0; nt < 4; nt++) {
                const float* br = vh + (k0 + t) * QK_STR + nt * 8 + g;
                uint32_t bb[2] = { fau(br[0]), fau(br[4 * QK_STR]) };
                mma8(acc[nt], a, bb);
            }
        }
        __syncthreads();   // attn reads done before r2 is overwritten with proj_w

#pragma unroll
        for (int nt = 0; nt < 4; nt++) {
            const int c0 = nt * 8 + 2 * t;
#pragma unroll
            for (int e = 0; e < 4; e++) {
                const int rr = r0 + ((e >= 2) ? 8 : 0);
                const int dd = c0 + (e & 1);
                xs[rr * XS_STR + h * 32 + dd] = f2tf(acc[nt][e]);
            }
        }
    }
    __syncthreads();

    // ---- Phase 6: final = o @ proj_w^T + proj_b ----
    {
        const float4* wg = (const float4*)proj_w;
        for (int i = tid; i < 128 * 32; i += THREADS) {
            int r = i >> 5, c4 = i & 31;
            float4 v = wg[r * 32 + c4];
            float* d = r2 + r * WS_STR + c4 * 4;
            d[0] = f2tf(v.x); d[1] = f2tf(v.y); d[2] = f2tf(v.z); d[3] = f2tf(v.w);
        }
        __syncthreads();

        const int mi = wid & 3;
        const int nq = wid >> 2;
        const int r0 = mi * 16 + g;

        float acc[4][4];
#pragma unroll
        for (int i = 0; i < 4; i++)
#pragma unroll
            for (int j = 0; j < 4; j++) acc[i][j] = 0.f;

#pragma unroll
        for (int ks = 0; ks < 16; ks++) {
            const int k0 = ks * 8;
            const float* ar = xs + r0 * XS_STR + k0 + t;
            uint32_t a[4] = { fau(ar[0]), fau(ar[8 * XS_STR]),
                              fau(ar[4]), fau(ar[8 * XS_STR + 4]) };
#pragma unroll
            for (int nt = 0; nt < 4; nt++) {
                const float* br = r2 + (nq * 32 + nt * 8 + g) * WS_STR + k0 + t;
                uint32_t bb[2] = { fau(br[0]), fau(br[4]) };
                mma8(acc[nt], a, bb);
            }
        }

        // stage into smem (QKV region, free now) for coalesced global store
        float* os = s + QKV_OFF;      // [64][132]
#pragma unroll
        for (int nt = 0; nt < 4; nt++) {
            const int c0 = nq * 32 + nt * 8 + 2 * t;
#pragma unroll
            for (int e = 0; e < 4; e++) {
                const int rr = r0 + ((e >= 2) ? 8 : 0);
                const int cc = c0 + (e & 1);
                os[rr * XS_STR + cc] = acc[nt][e] + proj_b[cc];
            }
        }
        __syncthreads();

        float4* ob = (float4*)(out + (size_t)b * (NTOK * CDIM));
        for (int i = tid; i < NTOK * 32; i += THREADS) {
            int r = i >> 5, c4 = i & 31;
            const float* p = os + r * XS_STR + c4 * 4;
            ob[r * 32 + c4] = make_float4(p[0], p[1], p[2], p[3]);
        }
    }
}

extern "C" void kernel_launch(void* const* d_in, const int* in_sizes, int n_in,
                              void* d_out, int out_size)
{
    const float* x          = (const float*)d_in[0];
    const float* mask       = (const float*)d_in[1];
    const float* qkv_w      = (const float*)d_in[2];
    const float* qkv_b      = (const float*)d_in[3];
    const float* proj_w     = (const float*)d_in[4];
    const float* proj_b     = (const float*)d_in[5];
    const float* bias_table = (const float*)d_in[6];
    float* out = (float*)d_out;

    const int B = in_sizes[0] / (NTOK * CDIM);   // 8192
    const int smem_bytes = SMEM_FLOATS * (int)sizeof(float);

    cudaFuncSetAttribute(window_attn_tc,
                         cudaFuncAttributeMaxDynamicSharedMemorySize, smem_bytes);

    window_attn_tc<<<B, THREADS, smem_bytes>>>(
        x, mask, qkv_w, qkv_b, proj_w, proj_b, bias_table, out);
}